// round 2
// baseline (speedup 1.0000x reference)
#include <cuda_runtime.h>
#include <cstdint>

// Problem constants (fixed shapes from reference)
#define B_   32
#define D_   64
#define H_   64
#define W_   64
#define K_   512
#define HW_  (H_ * W_)               // 4096
#define NPTS (B_ * HW_)              // 131072
#define NELEM ((long long)NPTS * D_) // 8388608
#define TPB  256
#define GRID (NPTS / TPB)            // 512

__device__ double g_loss_accum;

__global__ void vq_zero_kernel() { g_loss_accum = 0.0; }

__global__ __launch_bounds__(TPB, 1)
void vq_main_kernel(const float* __restrict__ z,
                    const float* __restrict__ cb,
                    float* __restrict__ out) {
    // Dynamic smem: codebook [K*D] + ||e||^2 [K] + reduction scratch [32]
    extern __shared__ float smem[];
    float* s_cb  = smem;                 // 512*64 floats = 128 KB
    float* s_y   = smem + K_ * D_;       // 512 floats (sum e_i^2, sequential fp32)
    float* s_red = s_y + K_;             // 32 floats

    const int tid = threadIdx.x;

    // Stage codebook into smem (vectorized, coalesced)
    {
        const float4* g4 = reinterpret_cast<const float4*>(cb);
        float4* s4 = reinterpret_cast<float4*>(s_cb);
        #pragma unroll
        for (int i = tid; i < K_ * D_ / 4; i += TPB) s4[i] = g4[i];
    }
    __syncthreads();

    // y_k = sum_i fl(e_i^2), SEQUENTIAL fp32 adds (replicates XLA reduce order).
    // Intrinsics prevent mul+add contraction into fma.
    for (int k = tid; k < K_; k += TPB) {
        const float* e = s_cb + k * D_;
        float s = 0.f;
        #pragma unroll
        for (int c = 0; c < D_; c++) s = __fadd_rn(s, __fmul_rn(e[c], e[c]));
        s_y[k] = s;
    }
    __syncthreads();

    // One point per thread
    const int n  = blockIdx.x * TPB + tid;
    const int b  = n >> 12;          // / 4096
    const int hw = n & (HW_ - 1);
    const float* zp = z + (size_t)b * D_ * HW_ + hw;

    // Load this point's feature vector (coalesced across warp for each channel)
    float zr[D_];
    #pragma unroll
    for (int i = 0; i < D_; i++) zr[i] = __ldg(zp + (size_t)i * HW_);

    // x = sum_i fl(z_i^2), sequential fp32 adds (no fma)
    float x = 0.f;
    #pragma unroll
    for (int i = 0; i < D_; i++) x = __fadd_rn(x, __fmul_rn(zr[i], zr[i]));

    // Scan all codes. For each k:
    //   m_k = sequential fma chain over i=0..63  (Eigen/oneDNN gebp order)
    //   d_k = fl( fl(x + y_k) - 2*m_k )          (2*m_k is exact)
    // Strict < keeps FIRST index on ties (matches jnp.argmin).
    float best  = 3.4e38f;
    int   bestk = 0;
    const float4* cbv = reinterpret_cast<const float4*>(s_cb);

    for (int k = 0; k < K_; k += 4) {
        float a0 = 0.f, a1 = 0.f, a2 = 0.f, a3 = 0.f;
        const float4* r0 = cbv + (k + 0) * (D_ / 4);
        const float4* r1 = cbv + (k + 1) * (D_ / 4);
        const float4* r2 = cbv + (k + 2) * (D_ / 4);
        const float4* r3 = cbv + (k + 3) * (D_ / 4);
        #pragma unroll
        for (int i = 0; i < D_ / 4; i++) {
            float4 e0 = r0[i], e1 = r1[i], e2 = r2[i], e3 = r3[i];
            a0 = __fmaf_rn(zr[4*i+0], e0.x, a0);
            a1 = __fmaf_rn(zr[4*i+0], e1.x, a1);
            a2 = __fmaf_rn(zr[4*i+0], e2.x, a2);
            a3 = __fmaf_rn(zr[4*i+0], e3.x, a3);
            a0 = __fmaf_rn(zr[4*i+1], e0.y, a0);
            a1 = __fmaf_rn(zr[4*i+1], e1.y, a1);
            a2 = __fmaf_rn(zr[4*i+1], e2.y, a2);
            a3 = __fmaf_rn(zr[4*i+1], e3.y, a3);
            a0 = __fmaf_rn(zr[4*i+2], e0.z, a0);
            a1 = __fmaf_rn(zr[4*i+2], e1.z, a1);
            a2 = __fmaf_rn(zr[4*i+2], e2.z, a2);
            a3 = __fmaf_rn(zr[4*i+2], e3.z, a3);
            a0 = __fmaf_rn(zr[4*i+3], e0.w, a0);
            a1 = __fmaf_rn(zr[4*i+3], e1.w, a1);
            a2 = __fmaf_rn(zr[4*i+3], e2.w, a2);
            a3 = __fmaf_rn(zr[4*i+3], e3.w, a3);
        }
        float d0 = __fadd_rn(__fadd_rn(x, s_y[k + 0]), -__fmul_rn(2.f, a0));
        float d1 = __fadd_rn(__fadd_rn(x, s_y[k + 1]), -__fmul_rn(2.f, a1));
        float d2 = __fadd_rn(__fadd_rn(x, s_y[k + 2]), -__fmul_rn(2.f, a2));
        float d3 = __fadd_rn(__fadd_rn(x, s_y[k + 3]), -__fmul_rn(2.f, a3));
        if (d0 < best) { best = d0; bestk = k + 0; }
        if (d1 < best) { best = d1; bestk = k + 1; }
        if (d2 < best) { best = d2; bestk = k + 2; }
        if (d3 < best) { best = d3; bestk = k + 3; }
    }

    // Output: straight-through estimator as written: out = fl(z + fl(q - z))
    // Loss accumulation: sum (q - z)^2 in fp32 per point, reduce in double.
    float* op = out + (size_t)b * D_ * HW_ + hw;
    const float* e = s_cb + bestk * D_;
    float lsum = 0.f;
    #pragma unroll
    for (int i = 0; i < D_; i++) {
        float q  = e[i];
        float dd = __fadd_rn(q, -zr[i]);          // fl(q - z)
        lsum = __fmaf_rn(dd, dd, lsum);
        op[(size_t)i * HW_] = __fadd_rn(zr[i], dd); // fl(z + fl(q - z))
    }

    // Block reduction of lsum -> double atomic
    #pragma unroll
    for (int off = 16; off > 0; off >>= 1)
        lsum += __shfl_down_sync(0xffffffffu, lsum, off);
    __syncthreads();   // smem reuse barrier (codebook reads done)
    if ((tid & 31) == 0) s_red[tid >> 5] = lsum;
    __syncthreads();
    if (tid < 32) {
        float v = (tid < TPB / 32) ? s_red[tid] : 0.f;
        #pragma unroll
        for (int off = 16; off > 0; off >>= 1)
            v += __shfl_down_sync(0xffffffffu, v, off);
        if (tid == 0) atomicAdd(&g_loss_accum, (double)v);
    }
}

__global__ void vq_finalize_kernel(float* __restrict__ out, int loss_idx) {
    // loss = q_latent + 0.25 * e_latent; both equal mean((q-z)^2)
    out[loss_idx] = (float)(g_loss_accum * 1.25 / (double)NELEM);
}

extern "C" void kernel_launch(void* const* d_in, const int* in_sizes, int n_in,
                              void* d_out, int out_size) {
    const float* z  = (const float*)d_in[0];
    const float* cb = (const float*)d_in[1];
    float* out = (float*)d_out;

    const int smem_bytes = (K_ * D_ + K_ + 32) * sizeof(float); // 133248 B
    static bool attr_set = false;
    if (!attr_set) {
        cudaFuncSetAttribute(vq_main_kernel,
                             cudaFuncAttributeMaxDynamicSharedMemorySize,
                             smem_bytes);
        attr_set = true;
    }

    vq_zero_kernel<<<1, 1>>>();
    vq_main_kernel<<<GRID, TPB, smem_bytes>>>(z, cb, out);
    vq_finalize_kernel<<<1, 1>>>(out, out_size - 1);
}